// round 2
// baseline (speedup 1.0000x reference)
#include <cuda_runtime.h>
#include <cstdint>

// ---------------- problem constants ----------------
#define BQ      1800          // B*Q
#define QPERB   900
#define CCH     256
#define NCAM    6
#define HF      112
#define WF      200
#define HWF     (HF*WF)       // 22400
#define ZL      10
#define YL      128
#define XL      128
#define ZYX     (ZL*YL*XL)    // 163840
#define QMAX    13            // max queries per block in MLP kernel
#define NSM     148           // B200 SM count -> one balanced wave

// scratch (no cudaMalloc allowed)
__device__ float g_cam[BQ * CCH];
__device__ float g_lid[BQ * CCH];

// ============================================================
// Kernel A: projection + bilinear/trilinear sampling
// one block per query, one thread per channel
// ============================================================
__global__ void __launch_bounds__(256) sample_kernel(
    const float* __restrict__ ref,      // (B,Q,3)
    const float* __restrict__ img,      // (B,N,C,HF,WF)
    const float* __restrict__ lid,      // (B,C,Z,Y,X)
    const float* __restrict__ l2i)      // (B,N,4,4)
{
    const int gq = blockIdx.x;
    const int b  = gq / QPERB;
    const int tid = threadIdx.x;

    __shared__ float sWt[NCAM][4];
    __shared__ int   sIdx[NCAM][4];
    __shared__ int   sValid[NCAM];
    __shared__ float sLW[8];
    __shared__ int   sLI[8];

    if (tid < 7) {
        const float rx = ref[gq*3+0];
        const float ry = ref[gq*3+1];
        const float rz = ref[gq*3+2];
        if (tid < 6) {
            // abs point in lidar frame
            const float X3 = rx * 102.4f - 51.2f;
            const float Y3 = ry * 102.4f - 51.2f;
            const float Z3 = rz * 8.0f   - 5.0f;
            const float* L = l2i + (size_t)(b*NCAM + tid)*16;
            const float px = L[0]*X3 + L[1]*Y3 + L[2]*Z3  + L[3];
            const float py = L[4]*X3 + L[5]*Y3 + L[6]*Z3  + L[7];
            const float pz = L[8]*X3 + L[9]*Y3 + L[10]*Z3 + L[11];
            const bool  dm = pz > 1e-5f;
            const float d  = fmaxf(pz, 1e-5f);
            const float u  = 2.0f*(px/d)/1599.0f - 1.0f;   // W0-1
            const float v  = 2.0f*(py/d)/899.0f  - 1.0f;   // H0-1
            const bool val = dm && (u >= -1.0f) && (u <= 1.0f)
                                && (v >= -1.0f) && (v <= 1.0f);
            sValid[tid] = val ? 1 : 0;
            if (val) {
                const float x  = ((u + 1.0f)*(float)WF - 1.0f)*0.5f;
                const float y  = ((v + 1.0f)*(float)HF - 1.0f)*0.5f;
                const float x0 = floorf(x);
                const float y0 = floorf(y);
                #pragma unroll
                for (int t = 0; t < 4; t++) {
                    const float xi = x0 + (float)(t & 1);
                    const float yi = y0 + (float)(t >> 1);
                    float w = (1.0f - fabsf(x - xi)) * (1.0f - fabsf(y - yi));
                    const bool inb = (xi >= 0.0f) && (xi < (float)WF)
                                  && (yi >= 0.0f) && (yi < (float)HF);
                    int xc = min(max((int)xi, 0), WF-1);
                    int yc = min(max((int)yi, 0), HF-1);
                    sWt[tid][t]  = inb ? w : 0.0f;
                    sIdx[tid][t] = yc*WF + xc;
                }
            }
        } else {
            // lidar trilinear setup
            const float gx = rx*2.0f - 1.0f;
            const float gy = ry*2.0f - 1.0f;
            const float gz = rz*2.0f - 1.0f;
            const float x  = ((gx + 1.0f)*(float)XL - 1.0f)*0.5f;
            const float y  = ((gy + 1.0f)*(float)YL - 1.0f)*0.5f;
            const float z  = ((gz + 1.0f)*(float)ZL - 1.0f)*0.5f;
            const float x0 = floorf(x), y0 = floorf(y), z0 = floorf(z);
            #pragma unroll
            for (int t = 0; t < 8; t++) {
                const float xi = x0 + (float)(t & 1);
                const float yi = y0 + (float)((t >> 1) & 1);
                const float zi = z0 + (float)(t >> 2);
                float w = (1.0f - fabsf(x - xi)) * (1.0f - fabsf(y - yi))
                        * (1.0f - fabsf(z - zi));
                const bool inb = (xi >= 0.0f) && (xi < (float)XL)
                              && (yi >= 0.0f) && (yi < (float)YL)
                              && (zi >= 0.0f) && (zi < (float)ZL);
                int xc = min(max((int)xi, 0), XL-1);
                int yc = min(max((int)yi, 0), YL-1);
                int zc = min(max((int)zi, 0), ZL-1);
                sLW[t] = inb ? w : 0.0f;
                sLI[t] = (zc*YL + yc)*XL + xc;
            }
        }
    }
    __syncthreads();

    const int c = tid;
    const int nv = sValid[0]+sValid[1]+sValid[2]+sValid[3]+sValid[4]+sValid[5];

    float accc = 0.0f;
    #pragma unroll
    for (int n = 0; n < NCAM; n++) {
        if (sValid[n]) {
            const float* base = img + ((size_t)(b*NCAM + n)*CCH + c)*(size_t)HWF;
            accc += sWt[n][0]*base[sIdx[n][0]]
                  + sWt[n][1]*base[sIdx[n][1]]
                  + sWt[n][2]*base[sIdx[n][2]]
                  + sWt[n][3]*base[sIdx[n][3]];
        }
    }
    g_cam[(size_t)gq*CCH + c] = accc * (1.0f / (float)max(nv, 1));

    const float* lb = lid + ((size_t)(b*CCH + c))*(size_t)ZYX;
    float accl = 0.0f;
    #pragma unroll
    for (int t = 0; t < 8; t++) accl += sLW[t]*lb[sLI[t]];
    g_lid[(size_t)gq*CCH + c] = accl;
}

// ============================================================
// Kernel B: projections + gated fusion + LN MLP
// 148 blocks (one balanced wave); each handles 12-13 queries,
// padded to QMAX=13 for fully unrolled loops. thread = out channel.
// ============================================================
__global__ void __launch_bounds__(256) mlp_kernel(
    const float* __restrict__ query,
    const float* __restrict__ cam_w,  const float* __restrict__ cam_b,
    const float* __restrict__ lidar_w,const float* __restrict__ lidar_b,
    const float* __restrict__ att_w1, const float* __restrict__ att_b1,
    const float* __restrict__ att_w2, const float* __restrict__ att_b2,
    const float* __restrict__ fus_w1, const float* __restrict__ fus_b1,
    const float* __restrict__ ln_g,   const float* __restrict__ ln_b,
    const float* __restrict__ fus_w2, const float* __restrict__ fus_b2,
    float* __restrict__ out)
{
    __shared__ float sA[QMAX*CCH];   // query  -> gated camF (fused[:,0:256])
    __shared__ float sB[QMAX*CCH];   // camF   -> gated lidF (fused[:,256:512])
    __shared__ float sC[QMAX*CCH];   // lidF   -> relu(LN(t))
    __shared__ float sH[QMAX*64];
    __shared__ float sG[QMAX*2];
    __shared__ float sRed[2][QMAX][8];
    __shared__ float sMu[QMAX], sRs[QMAX];

    const int tid = threadIdx.x;
    const int gq0 = (int)(((long long)blockIdx.x * BQ) / NSM);
    const int gq1 = (int)(((long long)(blockIdx.x+1) * BQ) / NSM);
    const int nq  = gq1 - gq0;   // 12 or 13; gq0+QMAX <= BQ always

    // stage query / sampled features (QMAX rows; row overrun stays < BQ)
    {
        const float4* q4 = (const float4*)(query + (size_t)gq0*CCH);
        const float4* c4 = (const float4*)(g_cam + (size_t)gq0*CCH);
        const float4* l4 = (const float4*)(g_lid + (size_t)gq0*CCH);
        for (int i = tid; i < QMAX*CCH/4; i += 256) {
            ((float4*)sA)[i] = q4[i];
            ((float4*)sB)[i] = c4[i];
            ((float4*)sC)[i] = l4[i];
        }
    }
    __syncthreads();

    // attention hidden: h = relu(q @ att_w1 + b1), (QMAX,64)
    for (int i = tid; i < QMAX*64; i += 256) {
        const int q = i >> 6, t = i & 63;
        float acc = att_b1[t];
        const float* qq = sA + q*CCH;
        #pragma unroll 4
        for (int k = 0; k < CCH; k++) acc += qq[k]*att_w1[k*64 + t];
        sH[i] = fmaxf(acc, 0.0f);
    }
    __syncthreads();

    // gate: softmax over 2 logits
    if (tid < QMAX) {
        float l0 = att_b2[0], l1 = att_b2[1];
        const float* hh = sH + tid*64;
        #pragma unroll 4
        for (int k = 0; k < 64; k++) { l0 += hh[k]*att_w2[k*2]; l1 += hh[k]*att_w2[k*2+1]; }
        const float m = fmaxf(l0, l1);
        const float e0 = expf(l0 - m), e1 = expf(l1 - m);
        const float inv = 1.0f/(e0 + e1);
        sG[tid*2]   = e0*inv;
        sG[tid*2+1] = e1*inv;
    }
    __syncthreads();

    const int c = tid;
    float acc[QMAX];

    // ---- cam projection: read sB, write gated result into sA ----
    {
        const float bb = cam_b[c];
        #pragma unroll
        for (int q = 0; q < QMAX; q++) acc[q] = bb;
        for (int k = 0; k < CCH; k += 4) {
            const float w0 = cam_w[(k+0)*CCH + c];
            const float w1 = cam_w[(k+1)*CCH + c];
            const float w2 = cam_w[(k+2)*CCH + c];
            const float w3 = cam_w[(k+3)*CCH + c];
            #pragma unroll
            for (int q = 0; q < QMAX; q++) {
                const float4 f = *(const float4*)(sB + q*CCH + k);
                acc[q] += f.x*w0 + f.y*w1 + f.z*w2 + f.w*w3;
            }
        }
        __syncthreads();
        #pragma unroll
        for (int q = 0; q < QMAX; q++) sA[q*CCH + c] = sG[q*2]*acc[q];
    }
    __syncthreads();

    // ---- lidar projection: read sC, write gated result into sB ----
    {
        const float bb = lidar_b[c];
        #pragma unroll
        for (int q = 0; q < QMAX; q++) acc[q] = bb;
        for (int k = 0; k < CCH; k += 4) {
            const float w0 = lidar_w[(k+0)*CCH + c];
            const float w1 = lidar_w[(k+1)*CCH + c];
            const float w2 = lidar_w[(k+2)*CCH + c];
            const float w3 = lidar_w[(k+3)*CCH + c];
            #pragma unroll
            for (int q = 0; q < QMAX; q++) {
                const float4 f = *(const float4*)(sC + q*CCH + k);
                acc[q] += f.x*w0 + f.y*w1 + f.z*w2 + f.w*w3;
            }
        }
        __syncthreads();
        #pragma unroll
        for (int q = 0; q < QMAX; q++) sB[q*CCH + c] = sG[q*2+1]*acc[q];
    }
    __syncthreads();

    // ---- t = fused @ fus_w1 + b1  (fused = [sA | sB], K=512) ----
    {
        const float bb = fus_b1[c];
        #pragma unroll
        for (int q = 0; q < QMAX; q++) acc[q] = bb;
        for (int k = 0; k < CCH; k += 4) {
            const float w0 = fus_w1[(k+0)*CCH + c];
            const float w1 = fus_w1[(k+1)*CCH + c];
            const float w2 = fus_w1[(k+2)*CCH + c];
            const float w3 = fus_w1[(k+3)*CCH + c];
            #pragma unroll
            for (int q = 0; q < QMAX; q++) {
                const float4 f = *(const float4*)(sA + q*CCH + k);
                acc[q] += f.x*w0 + f.y*w1 + f.z*w2 + f.w*w3;
            }
        }
        for (int k = 0; k < CCH; k += 4) {
            const float w0 = fus_w1[(CCH + k+0)*CCH + c];
            const float w1 = fus_w1[(CCH + k+1)*CCH + c];
            const float w2 = fus_w1[(CCH + k+2)*CCH + c];
            const float w3 = fus_w1[(CCH + k+3)*CCH + c];
            #pragma unroll
            for (int q = 0; q < QMAX; q++) {
                const float4 f = *(const float4*)(sB + q*CCH + k);
                acc[q] += f.x*w0 + f.y*w1 + f.z*w2 + f.w*w3;
            }
        }
    }

    // ---- LayerNorm stats over c per query ----
    {
        const int lane = tid & 31, wrp = tid >> 5;
        #pragma unroll
        for (int q = 0; q < QMAX; q++) {
            float s = acc[q], s2 = acc[q]*acc[q];
            #pragma unroll
            for (int o = 16; o > 0; o >>= 1) {
                s  += __shfl_xor_sync(0xffffffffu, s,  o);
                s2 += __shfl_xor_sync(0xffffffffu, s2, o);
            }
            if (lane == 0) { sRed[0][q][wrp] = s; sRed[1][q][wrp] = s2; }
        }
        __syncthreads();
        if (tid < QMAX) {
            float s = 0.0f, s2 = 0.0f;
            #pragma unroll
            for (int w = 0; w < 8; w++) { s += sRed[0][tid][w]; s2 += sRed[1][tid][w]; }
            const float mu  = s * (1.0f/(float)CCH);
            const float var = s2 * (1.0f/(float)CCH) - mu*mu;
            sMu[tid] = mu;
            sRs[tid] = rsqrtf(var + 1e-5f);
        }
        __syncthreads();
        const float gc = ln_g[c], bc = ln_b[c];
        #pragma unroll
        for (int q = 0; q < QMAX; q++) {
            const float y = fmaxf((acc[q] - sMu[q])*sRs[q]*gc + bc, 0.0f);
            sC[q*CCH + c] = y;
        }
    }
    __syncthreads();

    // ---- out = y @ fus_w2 + b2 ----
    {
        const float bb = fus_b2[c];
        #pragma unroll
        for (int q = 0; q < QMAX; q++) acc[q] = bb;
        for (int k = 0; k < CCH; k += 4) {
            const float w0 = fus_w2[(k+0)*CCH + c];
            const float w1 = fus_w2[(k+1)*CCH + c];
            const float w2 = fus_w2[(k+2)*CCH + c];
            const float w3 = fus_w2[(k+3)*CCH + c];
            #pragma unroll
            for (int q = 0; q < QMAX; q++) {
                const float4 f = *(const float4*)(sC + q*CCH + k);
                acc[q] += f.x*w0 + f.y*w1 + f.z*w2 + f.w*w3;
            }
        }
        #pragma unroll
        for (int q = 0; q < QMAX; q++)
            if (q < nq)
                out[(size_t)(gq0 + q)*CCH + c] = acc[q];
    }
}

// ============================================================
extern "C" void kernel_launch(void* const* d_in, const int* in_sizes, int n_in,
                              void* d_out, int out_size)
{
    const float* query   = (const float*)d_in[0];
    const float* refpts  = (const float*)d_in[1];
    const float* img     = (const float*)d_in[2];
    const float* lidar   = (const float*)d_in[3];
    const float* l2i     = (const float*)d_in[4];
    const float* cam_w   = (const float*)d_in[5];
    const float* cam_b   = (const float*)d_in[6];
    const float* lidar_w = (const float*)d_in[7];
    const float* lidar_b = (const float*)d_in[8];
    const float* att_w1  = (const float*)d_in[9];
    const float* att_b1  = (const float*)d_in[10];
    const float* att_w2  = (const float*)d_in[11];
    const float* att_b2  = (const float*)d_in[12];
    const float* fus_w1  = (const float*)d_in[13];
    const float* fus_b1  = (const float*)d_in[14];
    const float* ln_g    = (const float*)d_in[15];
    const float* ln_b    = (const float*)d_in[16];
    const float* fus_w2  = (const float*)d_in[17];
    const float* fus_b2  = (const float*)d_in[18];
    float* out = (float*)d_out;

    sample_kernel<<<BQ, 256>>>(refpts, img, lidar, l2i);
    mlp_kernel<<<NSM, 256>>>(query,
        cam_w, cam_b, lidar_w, lidar_b,
        att_w1, att_b1, att_w2, att_b2,
        fus_w1, fus_b1, ln_g, ln_b, fus_w2, fus_b2,
        out);
}

// round 4
// speedup vs baseline: 1.1686x; 1.1686x over previous
#include <cuda_runtime.h>
#include <cstdint>

// ---------------- problem constants ----------------
#define BQ      1800          // B*Q
#define QPERB   900
#define CCH     256
#define NCAM    6
#define HF      112
#define WF      200
#define HWF     (HF*WF)       // 22400
#define ZL      10
#define YL      128
#define XL      128
#define ZYX     (ZL*YL*XL)    // 163840
#define QMAX    13            // max queries per block in MLP kernel
#define NSM     148           // one balanced wave
#define QPAD    20            // padded pair-row width (floats), 16B-aligned rows

// scratch (no cudaMalloc allowed)
__device__ float g_cam[BQ * CCH];
__device__ float g_lid[BQ * CCH];

// ============================================================
// Kernel A: projection + bilinear/trilinear sampling
// one block per query, one thread per channel
// ============================================================
__global__ void __launch_bounds__(256) sample_kernel(
    const float* __restrict__ ref,      // (B,Q,3)
    const float* __restrict__ img,      // (B,N,C,HF,WF)
    const float* __restrict__ lid,      // (B,C,Z,Y,X)
    const float* __restrict__ l2i)      // (B,N,4,4)
{
    const int gq = blockIdx.x;
    const int b  = gq / QPERB;
    const int tid = threadIdx.x;

    __shared__ float sWt[NCAM][4];
    __shared__ int   sIdx[NCAM][4];
    __shared__ int   sValid[NCAM];
    __shared__ float sLW[8];
    __shared__ int   sLI[8];

    if (tid < 7) {
        const float rx = ref[gq*3+0];
        const float ry = ref[gq*3+1];
        const float rz = ref[gq*3+2];
        if (tid < 6) {
            const float X3 = rx * 102.4f - 51.2f;
            const float Y3 = ry * 102.4f - 51.2f;
            const float Z3 = rz * 8.0f   - 5.0f;
            const float* L = l2i + (size_t)(b*NCAM + tid)*16;
            const float px = L[0]*X3 + L[1]*Y3 + L[2]*Z3  + L[3];
            const float py = L[4]*X3 + L[5]*Y3 + L[6]*Z3  + L[7];
            const float pz = L[8]*X3 + L[9]*Y3 + L[10]*Z3 + L[11];
            const bool  dm = pz > 1e-5f;
            const float d  = fmaxf(pz, 1e-5f);
            const float u  = 2.0f*(px/d)/1599.0f - 1.0f;
            const float v  = 2.0f*(py/d)/899.0f  - 1.0f;
            const bool val = dm && (u >= -1.0f) && (u <= 1.0f)
                                && (v >= -1.0f) && (v <= 1.0f);
            sValid[tid] = val ? 1 : 0;
            if (val) {
                const float x  = ((u + 1.0f)*(float)WF - 1.0f)*0.5f;
                const float y  = ((v + 1.0f)*(float)HF - 1.0f)*0.5f;
                const float x0 = floorf(x);
                const float y0 = floorf(y);
                #pragma unroll
                for (int t = 0; t < 4; t++) {
                    const float xi = x0 + (float)(t & 1);
                    const float yi = y0 + (float)(t >> 1);
                    float w = (1.0f - fabsf(x - xi)) * (1.0f - fabsf(y - yi));
                    const bool inb = (xi >= 0.0f) && (xi < (float)WF)
                                  && (yi >= 0.0f) && (yi < (float)HF);
                    int xc = min(max((int)xi, 0), WF-1);
                    int yc = min(max((int)yi, 0), HF-1);
                    sWt[tid][t]  = inb ? w : 0.0f;
                    sIdx[tid][t] = yc*WF + xc;
                }
            }
        } else {
            const float gx = rx*2.0f - 1.0f;
            const float gy = ry*2.0f - 1.0f;
            const float gz = rz*2.0f - 1.0f;
            const float x  = ((gx + 1.0f)*(float)XL - 1.0f)*0.5f;
            const float y  = ((gy + 1.0f)*(float)YL - 1.0f)*0.5f;
            const float z  = ((gz + 1.0f)*(float)ZL - 1.0f)*0.5f;
            const float x0 = floorf(x), y0 = floorf(y), z0 = floorf(z);
            #pragma unroll
            for (int t = 0; t < 8; t++) {
                const float xi = x0 + (float)(t & 1);
                const float yi = y0 + (float)((t >> 1) & 1);
                const float zi = z0 + (float)(t >> 2);
                float w = (1.0f - fabsf(x - xi)) * (1.0f - fabsf(y - yi))
                        * (1.0f - fabsf(z - zi));
                const bool inb = (xi >= 0.0f) && (xi < (float)XL)
                              && (yi >= 0.0f) && (yi < (float)YL)
                              && (zi >= 0.0f) && (zi < (float)ZL);
                int xc = min(max((int)xi, 0), XL-1);
                int yc = min(max((int)yi, 0), YL-1);
                int zc = min(max((int)zi, 0), ZL-1);
                sLW[t] = inb ? w : 0.0f;
                sLI[t] = (zc*YL + yc)*XL + xc;
            }
        }
    }
    __syncthreads();

    const int c = tid;
    const int nv = sValid[0]+sValid[1]+sValid[2]+sValid[3]+sValid[4]+sValid[5];

    float accc = 0.0f;
    #pragma unroll
    for (int n = 0; n < NCAM; n++) {
        if (sValid[n]) {
            const float* base = img + ((size_t)(b*NCAM + n)*CCH + c)*(size_t)HWF;
            accc += sWt[n][0]*base[sIdx[n][0]]
                  + sWt[n][1]*base[sIdx[n][1]]
                  + sWt[n][2]*base[sIdx[n][2]]
                  + sWt[n][3]*base[sIdx[n][3]];
        }
    }
    g_cam[(size_t)gq*CCH + c] = accc * (1.0f / (float)max(nv, 1));

    const float* lb = lid + ((size_t)(b*CCH + c))*(size_t)ZYX;
    float accl = 0.0f;
    #pragma unroll
    for (int t = 0; t < 8; t++) accl += sLW[t]*lb[sLI[t]];
    g_lid[(size_t)gq*CCH + c] = accl;
}

// ============================================================
// packed f32x2 helpers
// ============================================================
__device__ __forceinline__ unsigned long long pack2(float x, float y) {
    unsigned long long r;
    asm("mov.b64 %0, {%1,%2};" : "=l"(r)
        : "r"(__float_as_uint(x)), "r"(__float_as_uint(y)));
    return r;
}
__device__ __forceinline__ void unpack2(unsigned long long v, float& x, float& y) {
    unsigned lo, hi;
    asm("mov.b64 {%0,%1}, %2;" : "=r"(lo), "=r"(hi) : "l"(v));
    x = __uint_as_float(lo); y = __uint_as_float(hi);
}
#define FMA2(acc, a, b) asm("fma.rn.f32x2 %0, %1, %2, %0;" : "+l"(acc) : "l"(a), "l"(b))
#define MUL2(d, a, b)   asm("mul.rn.f32x2 %0, %1, %2;" : "=l"(d) : "l"(a), "l"(b))

// One 256-k GEMV pass: acc[p] (7 query-pairs) += actT^T * W[:,c]
// W: [256][256] row-major (k-major). actT: smem [256][QPAD] pair-packed.
// Distance-2 software-pipelined weight prefetch.
__device__ __forceinline__ void gemv_f32x2(
    const float* __restrict__ W, const float* sT, int c,
    unsigned long long acc[7])
{
    const float* wp = W + c;
    float a0 = wp[0],    a1 = wp[256],  a2 = wp[512],  a3 = wp[768];
    float b0 = wp[1024], b1 = wp[1280], b2 = wp[1536], b3 = wp[1792];

    #pragma unroll 2
    for (int kg = 0; kg < 64; kg++) {
        float c0 = 0.f, c1 = 0.f, c2 = 0.f, c3 = 0.f;
        if (kg < 62) {
            const float* wn = wp + 2048;
            c0 = wn[0]; c1 = wn[256]; c2 = wn[512]; c3 = wn[768];
        }
        const float* row = sT + kg*4*QPAD;
        #define KSTEP(wv, j) { \
            unsigned long long wpk = pack2(wv, wv); \
            const float* r_ = row + (j)*QPAD; \
            ulonglong2 p01 = *(const ulonglong2*)(r_); \
            ulonglong2 p23 = *(const ulonglong2*)(r_ + 4); \
            ulonglong2 p45 = *(const ulonglong2*)(r_ + 8); \
            unsigned long long p6 = *(const unsigned long long*)(r_ + 12); \
            FMA2(acc[0], p01.x, wpk); FMA2(acc[1], p01.y, wpk); \
            FMA2(acc[2], p23.x, wpk); FMA2(acc[3], p23.y, wpk); \
            FMA2(acc[4], p45.x, wpk); FMA2(acc[5], p45.y, wpk); \
            FMA2(acc[6], p6,    wpk); }
        KSTEP(a0, 0) KSTEP(a1, 1) KSTEP(a2, 2) KSTEP(a3, 3)
        #undef KSTEP
        a0 = b0; a1 = b1; a2 = b2; a3 = b3;
        b0 = c0; b1 = c1; b2 = c2; b3 = c3;
        wp += 1024;
    }
}

// ============================================================
// Kernel B: projections + gated fusion + LN MLP
// grid=148, 256 thr; thread = output channel; 12-13 queries/block
// activations pair-packed in transposed smem; f32x2 FMA throughout
// ============================================================
__global__ void __launch_bounds__(256) mlp_kernel(
    const float* __restrict__ query,
    const float* __restrict__ cam_w,  const float* __restrict__ cam_b,
    const float* __restrict__ lidar_w,const float* __restrict__ lidar_b,
    const float* __restrict__ att_w1, const float* __restrict__ att_b1,
    const float* __restrict__ att_w2, const float* __restrict__ att_b2,
    const float* __restrict__ fus_w1, const float* __restrict__ fus_b1,
    const float* __restrict__ ln_g,   const float* __restrict__ ln_b,
    const float* __restrict__ fus_w2, const float* __restrict__ fus_b2,
    float* __restrict__ out)
{
    __shared__ __align__(16) float sCamT[CCH*QPAD];
    __shared__ __align__(16) float sLidT[CCH*QPAD];
    __shared__ float sH[QMAX*64];
    __shared__ float sG[32];
    __shared__ float sRed[2][QMAX][8];
    __shared__ float sMu[16], sRs[16];

    const int tid = threadIdx.x;
    const int gq0 = (int)(((long long)blockIdx.x * BQ) / NSM);
    const int gq1 = (int)(((long long)(blockIdx.x+1) * BQ) / NSM);
    const int nq  = gq1 - gq0;   // 12 or 13; gq0+13 <= 1800 always

    // ---- stage transposed pair-packed activations (zero-pad q=13..15) ----
    {
        const float4* c4 = (const float4*)(g_cam + (size_t)gq0*CCH);
        const float4* l4 = (const float4*)(g_lid + (size_t)gq0*CCH);
        #pragma unroll
        for (int it = 0; it < 4; it++) {
            const int i  = tid + it*256;      // i = q*64 + kg, q in 0..15
            const int q  = i >> 6;
            const int kg = i & 63;
            float4 vc = make_float4(0.f,0.f,0.f,0.f);
            float4 vl = make_float4(0.f,0.f,0.f,0.f);
            if (q < QMAX) { vc = c4[q*64 + kg]; vl = l4[q*64 + kg]; }
            const int base = (4*kg)*QPAD + q;
            sCamT[base         ] = vc.x;
            sCamT[base +   QPAD] = vc.y;
            sCamT[base + 2*QPAD] = vc.z;
            sCamT[base + 3*QPAD] = vc.w;
            sLidT[base         ] = vl.x;
            sLidT[base +   QPAD] = vl.y;
            sLidT[base + 2*QPAD] = vl.z;
            sLidT[base + 3*QPAD] = vl.w;
        }
    }

    // ---- attention hidden (reads query/weights from global only) ----
    for (int i = tid; i < QMAX*64; i += 256) {
        const int q = i >> 6, t = i & 63;
        const float* qq = query + (size_t)(gq0 + q)*CCH;
        float acc = att_b1[t];
        #pragma unroll 8
        for (int k = 0; k < CCH; k++) acc += qq[k]*att_w1[k*64 + t];
        sH[i] = fmaxf(acc, 0.0f);
    }
    __syncthreads();

    // ---- gate softmax ----
    if (tid < 16) {
        if (tid < QMAX) {
            float l0 = att_b2[0], l1 = att_b2[1];
            const float* hh = sH + tid*64;
            #pragma unroll 8
            for (int k = 0; k < 64; k++) {
                l0 += hh[k]*att_w2[k*2];
                l1 += hh[k]*att_w2[k*2+1];
            }
            const float m = fmaxf(l0, l1);
            const float e0 = expf(l0 - m), e1 = expf(l1 - m);
            const float inv = 1.0f/(e0 + e1);
            sG[tid*2]   = e0*inv;
            sG[tid*2+1] = e1*inv;
        } else {
            sG[tid*2] = 0.f; sG[tid*2+1] = 0.f;
        }
    }
    __syncthreads();

    const int c = tid;
    unsigned long long acc[7];

    // ---- cam projection ----
    {
        const unsigned long long b2 = pack2(cam_b[c], cam_b[c]);
        #pragma unroll
        for (int p = 0; p < 7; p++) acc[p] = b2;
        gemv_f32x2(cam_w, sCamT, c, acc);
    }
    __syncthreads();                       // all reads of sCamT done
    #pragma unroll
    for (int p = 0; p < 7; p++) {          // gated cam -> sCamT row c
        unsigned long long g2 = pack2(sG[4*p], sG[4*p + 2]);
        unsigned long long r; MUL2(r, acc[p], g2);
        *(unsigned long long*)(sCamT + c*QPAD + 2*p) = r;
    }

    // ---- lidar projection ----
    {
        const unsigned long long b2 = pack2(lidar_b[c], lidar_b[c]);
        #pragma unroll
        for (int p = 0; p < 7; p++) acc[p] = b2;
        gemv_f32x2(lidar_w, sLidT, c, acc);
    }
    __syncthreads();                       // all reads of sLidT done; cam stores visible
    #pragma unroll
    for (int p = 0; p < 7; p++) {          // gated lid -> sLidT row c
        unsigned long long g2 = pack2(sG[4*p + 1], sG[4*p + 3]);
        unsigned long long r; MUL2(r, acc[p], g2);
        *(unsigned long long*)(sLidT + c*QPAD + 2*p) = r;
    }
    __syncthreads();                       // lid stores visible

    // ---- fus1 (K=512) ----
    {
        const unsigned long long b2 = pack2(fus_b1[c], fus_b1[c]);
        #pragma unroll
        for (int p = 0; p < 7; p++) acc[p] = b2;
        gemv_f32x2(fus_w1,             sCamT, c, acc);
        gemv_f32x2(fus_w1 + CCH*CCH,   sLidT, c, acc);
    }

    // ---- LayerNorm ----
    float t[14];
    #pragma unroll
    for (int p = 0; p < 7; p++) unpack2(acc[p], t[2*p], t[2*p+1]);
    {
        const int lane = tid & 31, wrp = tid >> 5;
        #pragma unroll
        for (int q = 0; q < QMAX; q++) {
            float s = t[q], s2 = t[q]*t[q];
            #pragma unroll
            for (int o = 16; o > 0; o >>= 1) {
                s  += __shfl_xor_sync(0xffffffffu, s,  o);
                s2 += __shfl_xor_sync(0xffffffffu, s2, o);
            }
            if (lane == 0) { sRed[0][q][wrp] = s; sRed[1][q][wrp] = s2; }
        }
        __syncthreads();                   // also: everyone done reading sCamT/sLidT
        if (tid < 16) {
            if (tid < QMAX) {
                float s = 0.f, s2 = 0.f;
                #pragma unroll
                for (int w = 0; w < 8; w++) { s += sRed[0][tid][w]; s2 += sRed[1][tid][w]; }
                const float mu  = s * (1.0f/(float)CCH);
                const float var = s2 * (1.0f/(float)CCH) - mu*mu;
                sMu[tid] = mu;
                sRs[tid] = rsqrtf(var + 1e-5f);
            } else { sMu[tid] = 0.f; sRs[tid] = 1.f; }
        }
        __syncthreads();
    }
    {
        const float gc = ln_g[c], bc = ln_b[c];
        float y[14];
        #pragma unroll
        for (int q = 0; q < 14; q++)
            y[q] = fmaxf((t[q] - sMu[q])*sRs[q]*gc + bc, 0.0f);
        #pragma unroll
        for (int p = 0; p < 7; p++)
            *(unsigned long long*)(sCamT + c*QPAD + 2*p) = pack2(y[2*p], y[2*p+1]);
    }
    __syncthreads();

    // ---- fus2 + store ----
    {
        const unsigned long long b2 = pack2(fus_b2[c], fus_b2[c]);
        #pragma unroll
        for (int p = 0; p < 7; p++) acc[p] = b2;
        gemv_f32x2(fus_w2, sCamT, c, acc);
    }
    #pragma unroll
    for (int p = 0; p < 7; p++) {
        float lo, hi; unpack2(acc[p], lo, hi);
        const int q0 = 2*p, q1 = 2*p + 1;
        if (q0 < nq) out[(size_t)(gq0 + q0)*CCH + c] = lo;
        if (q1 < nq) out[(size_t)(gq0 + q1)*CCH + c] = hi;
    }
}

// ============================================================
extern "C" void kernel_launch(void* const* d_in, const int* in_sizes, int n_in,
                              void* d_out, int out_size)
{
    const float* query   = (const float*)d_in[0];
    const float* refpts  = (const float*)d_in[1];
    const float* img     = (const float*)d_in[2];
    const float* lidar   = (const float*)d_in[3];
    const float* l2i     = (const float*)d_in[4];
    const float* cam_w   = (const float*)d_in[5];
    const float* cam_b   = (const float*)d_in[6];
    const float* lidar_w = (const float*)d_in[7];
    const float* lidar_b = (const float*)d_in[8];
    const float* att_w1  = (const float*)d_in[9];
    const float* att_b1  = (const float*)d_in[10];
    const float* att_w2  = (const float*)d_in[11];
    const float* att_b2  = (const float*)d_in[12];
    const float* fus_w1  = (const float*)d_in[13];
    const float* fus_b1  = (const float*)d_in[14];
    const float* ln_g    = (const float*)d_in[15];
    const float* ln_b    = (const float*)d_in[16];
    const float* fus_w2  = (const float*)d_in[17];
    const float* fus_b2  = (const float*)d_in[18];
    float* out = (float*)d_out;

    sample_kernel<<<BQ, 256>>>(refpts, img, lidar, l2i);
    mlp_kernel<<<NSM, 256>>>(query,
        cam_w, cam_b, lidar_w, lidar_b,
        att_w1, att_b1, att_w2, att_b2,
        fus_w1, fus_b1, ln_g, ln_b, fus_w2, fus_b2,
        out);
}